// round 1
// baseline (speedup 1.0000x reference)
#include <cuda_runtime.h>

#define NBINS 8192
#define N_LEV 1024
#define XMIN_F (-4.25f)
#define XMAX_F (4.25f)

__device__ float    g_grid[N_LEV];
__device__ float    g_lut[N_LEV];
__device__ unsigned g_bins[NBINS];

// ---------------------------------------------------------------------------
// Prep 1: extract grid = h[:,0] and build the per-level output LUT.
// Reference: v = grid[i]; for t=1..8: out += (v - T[t] >= 0) * d[t];
//            if t != 8: v = h[i, t+1];  out -= b.
// ---------------------------------------------------------------------------
__global__ void prep_lut(const float* __restrict__ h,
                         const float* __restrict__ d,
                         const float* __restrict__ T,
                         const float* __restrict__ b)
{
    int i = threadIdx.x;  // 1024 threads, 1 block
    float v = h[i * 9 + 0];
    g_grid[i] = v;
    float out = 0.0f;
#pragma unroll
    for (int t = 1; t <= 8; ++t) {
        if (v - T[t] >= 0.0f) out += d[t];
        if (t != 8) v = h[i * 9 + t + 1];
    }
    g_lut[i] = out - b[0];
}

// Exact reference nearest-index (searchsorted 'left' + abs compare).
__device__ __forceinline__ int nidx_exact(float x)
{
    int l = 0, r = N_LEV;                 // first i with grid[i] >= x
    while (l < r) {
        int m = (l + r) >> 1;
        if (__ldg(&g_grid[m]) < x) l = m + 1; else r = m;
    }
    int idx = l < 1 ? 1 : (l > N_LEV - 1 ? N_LEV - 1 : l);
    float left  = __ldg(&g_grid[idx - 1]);
    float right = __ldg(&g_grid[idx]);
    return (fabsf(x - left) < fabsf(x - right)) ? idx - 1 : idx;
}

// ---------------------------------------------------------------------------
// Prep 2: per-bin table. Widened edges (margin >> fp rounding of the bin
// quantizer) guarantee lo <= nidx(x) <= hi for every x mapping to bin j.
// Unambiguous bin -> store final output float directly.
// Ambiguous -> store (lo,hi) in negative-NaN space (never a legit output).
// ---------------------------------------------------------------------------
__global__ void prep_bins()
{
    int j = blockIdx.x * blockDim.x + threadIdx.x;
    if (j >= NBINS) return;
    const float W = (XMAX_F - XMIN_F) / (float)NBINS;
    float eL = XMIN_F + (float)j       * W - 0.25f * W;
    float eR = XMIN_F + (float)(j + 1) * W + 0.25f * W;
    int lo = nidx_exact(eL);
    int hi = nidx_exact(eR);
    if (lo == hi)
        g_bins[j] = __float_as_uint(g_lut[lo]);
    else
        g_bins[j] = 0xFFC00000u | ((unsigned)lo << 10) | (unsigned)hi;
}

// ---------------------------------------------------------------------------
// Main kernel
// ---------------------------------------------------------------------------
__device__ __forceinline__ float eval_one(float x,
                                          const unsigned* __restrict__ s_bins,
                                          const float* __restrict__ s_grid,
                                          const float* __restrict__ s_lut)
{
    const float scale = (float)NBINS / (XMAX_F - XMIN_F);
    float t = (x - XMIN_F) * scale;
    int j = (int)t;
    j = j < 0 ? 0 : (j > NBINS - 1 ? NBINS - 1 : j);
    unsigned u = s_bins[j];
    if (u < 0xFFC00000u) return __uint_as_float(u);   // fast path (~85%)
    int nidx = (int)((u >> 10) & 1023u);
    int hi   = (int)(u & 1023u);
    float gl = s_grid[nidx];
    while (nidx < hi) {                                // usually 0-1 iters
        float gr = s_grid[nidx + 1];
        if (fabsf(x - gl) < fabsf(x - gr)) break;      // exact ref tie-break
        ++nidx; gl = gr;
    }
    return s_lut[nidx];
}

__global__ void __launch_bounds__(256, 5)
ps_act_main(const float4* __restrict__ xin, float4* __restrict__ oout,
            int n4, const float* __restrict__ xs, float* __restrict__ os, int n)
{
    __shared__ unsigned s_bins[NBINS];
    __shared__ float    s_grid[N_LEV];
    __shared__ float    s_lut[N_LEV];

    for (int i = threadIdx.x; i < NBINS; i += blockDim.x) s_bins[i] = g_bins[i];
    for (int i = threadIdx.x; i < N_LEV; i += blockDim.x) {
        s_grid[i] = g_grid[i];
        s_lut[i]  = g_lut[i];
    }
    __syncthreads();

    int tid     = blockIdx.x * blockDim.x + threadIdx.x;
    int nthread = gridDim.x * blockDim.x;

    // 2 float4 per iteration for memory-level parallelism
    int stride2 = nthread * 2;
    int i;
    for (i = tid * 2; i + 1 < n4; i += stride2) {
        float4 a = xin[i];
        float4 b = xin[i + 1];
        float4 ra, rb;
        ra.x = eval_one(a.x, s_bins, s_grid, s_lut);
        ra.y = eval_one(a.y, s_bins, s_grid, s_lut);
        ra.z = eval_one(a.z, s_bins, s_grid, s_lut);
        ra.w = eval_one(a.w, s_bins, s_grid, s_lut);
        rb.x = eval_one(b.x, s_bins, s_grid, s_lut);
        rb.y = eval_one(b.y, s_bins, s_grid, s_lut);
        rb.z = eval_one(b.z, s_bins, s_grid, s_lut);
        rb.w = eval_one(b.w, s_bins, s_grid, s_lut);
        oout[i]     = ra;
        oout[i + 1] = rb;
    }
    if (i < n4) {  // odd leftover float4
        float4 a = xin[i];
        float4 ra;
        ra.x = eval_one(a.x, s_bins, s_grid, s_lut);
        ra.y = eval_one(a.y, s_bins, s_grid, s_lut);
        ra.z = eval_one(a.z, s_bins, s_grid, s_lut);
        ra.w = eval_one(a.w, s_bins, s_grid, s_lut);
        oout[i] = ra;
    }

    // scalar tail (n not divisible by 4)
    for (int k = n4 * 4 + tid; k < n; k += nthread)
        os[k] = eval_one(xs[k], s_bins, s_grid, s_lut);
}

// ---------------------------------------------------------------------------
extern "C" void kernel_launch(void* const* d_in, const int* in_sizes, int n_in,
                              void* d_out, int out_size)
{
    const float* x = (const float*)d_in[0];
    const float* h = (const float*)d_in[1];
    const float* d = (const float*)d_in[2];
    const float* T = (const float*)d_in[3];
    const float* b = (const float*)d_in[4];
    float* out = (float*)d_out;
    int n  = in_sizes[0];
    int n4 = n >> 2;

    prep_lut<<<1, 1024>>>(h, d, T, b);
    prep_bins<<<NBINS / 256, 256>>>();

    int blocks = 760;  // 5 CTAs/SM on 152 SMs, single wave
    ps_act_main<<<blocks, 256>>>((const float4*)x, (float4*)out, n4, x, out, n);
}